// round 11
// baseline (speedup 1.0000x reference)
#include <cuda_runtime.h>

#define BB 64
#define CC 16
#define HH 32
#define WW 512
#define NS 9      // shifts: off = s - 4
#define CT 4      // channels per cp.async tile
#define GRIDX 608 // 152 SMs * 4 CTAs, persistent
#define NROWS (BB * HH)

// Per-(pair,b,s,h) partials — pure writes, no zeroing / atomics.
__device__ float g_pnum[2][BB][NS][HH];
__device__ float g_pcnt[2][BB][NS][HH];
__device__ float g_bloss[BB];

typedef unsigned long long ull;

__device__ __forceinline__ void cp_async16(unsigned int sdst, const void* gsrc) {
    asm volatile("cp.async.cg.shared.global [%0], [%1], 16;\n" :: "r"(sdst), "l"(gsrc));
}
__device__ __forceinline__ void cp_commit() {
    asm volatile("cp.async.commit_group;\n" ::: "memory");
}
template <int N> __device__ __forceinline__ void cp_wait() {
    asm volatile("cp.async.wait_group %0;\n" :: "n"(N) : "memory");
}

// Packed fp32x2 helpers (sm_103a FFMA2 — PTX only)
__device__ __forceinline__ ull pk2(float lo, float hi) {
    ull r; asm("mov.b64 %0, {%1, %2};" : "=l"(r) : "f"(lo), "f"(hi)); return r;
}
__device__ __forceinline__ float2 upk(ull v) {
    float2 f; asm("mov.b64 {%0, %1}, %2;" : "=f"(f.x), "=f"(f.y) : "l"(v)); return f;
}
__device__ __forceinline__ void ffma2(ull& d, ull a, ull b) {
    asm("fma.rn.f32x2 %0, %1, %2, %0;" : "+l"(d) : "l"(a), "l"(b));
}

__device__ __forceinline__ void load_mask4f(const char* __restrict__ m, unsigned base,
                                            int mode, float out[4]) {
    if (mode == 0) {
        uchar4 v = *reinterpret_cast<const uchar4*>(m + base);
        out[0] = v.x ? 1.f : 0.f; out[1] = v.y ? 1.f : 0.f;
        out[2] = v.z ? 1.f : 0.f; out[3] = v.w ? 1.f : 0.f;
    } else if (mode == 1) {
        int4 v = *reinterpret_cast<const int4*>(reinterpret_cast<const int*>(m) + base);
        out[0] = v.x ? 1.f : 0.f; out[1] = v.y ? 1.f : 0.f;
        out[2] = v.z ? 1.f : 0.f; out[3] = v.w ? 1.f : 0.f;
    } else {
        float4 v = *reinterpret_cast<const float4*>(reinterpret_cast<const float*>(m) + base);
        out[0] = v.x != 0.f ? 1.f : 0.f; out[1] = v.y != 0.f ? 1.f : 0.f;
        out[2] = v.z != 0.f ? 1.f : 0.f; out[3] = v.w != 0.f ? 1.f : 0.f;
    }
}

// ---------------------------------------------------------------------------
// Persistent kernel: 608 CTAs, each processes rows bid, bid+608, ...
// Per row: one (b,h); 128 threads, 4 consecutive w per thread.
// f rows streamed as 8 KB channel-tiles (cp.async ring, depth 3) that runs
// across row boundaries; next row's A/masks prefetched under the epilogue.
// ---------------------------------------------------------------------------
__global__ void __launch_bounds__(128, 4) loss_kernel(
    const float* __restrict__ A, const float* __restrict__ P,
    const float* __restrict__ Nt,
    const char* __restrict__ MA, const char* __restrict__ MP,
    const char* __restrict__ MN)
{
    __shared__ __align__(16) float ring[4][CT][WW];     // 32 KB
    __shared__ __align__(16) float sSb[WW];             // 2 KB
    __shared__ __align__(16) float smA[2][WW];          // 4 KB (double-buffered)
    __shared__ __align__(16) float smF[2][2][WW];       // 8 KB [buf][pair][w]
    __shared__ __align__(16) float redN[2][NS][16], redC[2][NS][16];
    __shared__ unsigned int sflag[4];

    const int t  = threadIdx.x;
    const int wid = t >> 5, lane = t & 31;
    const int w0 = t * 4;
    const int e0 = (w0 - 4) & (WW - 1);
    const int e2 = (w0 + 4) & (WW - 1);

    // -- mask dtype sniff (once per CTA; deterministic, identical everywhere)
    if (t < 64) {
        unsigned int w = reinterpret_cast<const unsigned int*>(MA)[t];
        unsigned int bf = __ballot_sync(0xffffffffu, w == 0x3F800000u);
        unsigned int bg = __ballot_sync(0xffffffffu, (w >> 8) != 0u);
        if (lane == 0) { sflag[t >> 5] = bf; sflag[2 + (t >> 5)] = bg; }
    }

    auto row_base = [](int row) -> unsigned {
        return (unsigned)(((row >> 5) * CC * HH + (row & 31)) * WW);
    };

    auto issue_tile = [&](unsigned base, int j) {   // j = tile idx within row
        const float* F = (j >= 4) ? Nt : P;
        const int ct = j & 3, buf = j & 3;
#pragma unroll
        for (int cc = 0; cc < CT; cc++)
            cp_async16((unsigned int)__cvta_generic_to_shared(&ring[buf][cc][w0]),
                       F + base + (size_t)(ct * CT + cc) * HH * WW + w0);
        cp_commit();
    };

    int row = blockIdx.x;
    unsigned cur = row_base(row);
    int nrow = row + GRIDX;
    bool hasnext = nrow < NROWS;
    unsigned nxt = hasnext ? row_base(nrow) : 0;

    // Prime the pipe: tiles 0..2 of first row (P channels 0..11)
    issue_tile(cur, 0); issue_tile(cur, 1); issue_tile(cur, 2);
    __syncthreads();
    const int mode = (sflag[0] | sflag[1]) ? 2 : ((sflag[2] | sflag[3]) ? 0 : 1);

    // First row's A + Sa + masks (overlaps in-flight tiles)
    float4 av[CC];
    float Sa[4];
    {
        ull s0 = pk2(0.f, 0.f), s1 = s0;
#pragma unroll
        for (int c = 0; c < CC; c++) {
            float4 v = *reinterpret_cast<const float4*>(A + cur + (size_t)c * HH * WW + w0);
            av[c] = v;
            ull va = pk2(v.x, v.y), vb = pk2(v.z, v.w);
            ffma2(s0, va, va); ffma2(s1, vb, vb);
        }
        float2 f = upk(s0); Sa[0] = f.x; Sa[1] = f.y;
        f = upk(s1);        Sa[2] = f.x; Sa[3] = f.y;
    }
    {
        unsigned mrow = (unsigned)(((row >> 5) * HH + (row & 31)) * WW);
        float m4[4];
        load_mask4f(MA, mrow + w0, mode, m4);
        *reinterpret_cast<float4*>(&smA[0][w0]) = make_float4(m4[0], m4[1], m4[2], m4[3]);
        load_mask4f(MP, mrow + w0, mode, m4);
        *reinterpret_cast<float4*>(&smF[0][0][w0]) = make_float4(m4[0], m4[1], m4[2], m4[3]);
        load_mask4f(MN, mrow + w0, mode, m4);
        *reinterpret_cast<float4*>(&smF[0][1][w0]) = make_float4(m4[0], m4[1], m4[2], m4[3]);
    }

    // Accumulators: even s packed along j-pairs, odd s scalar.
    ull  X2a[5], X2b[5];
    float Xo[4][4];
    ull  sb2[2];
    const ull z2 = pk2(0.f, 0.f);
#pragma unroll
    for (int m = 0; m < 5; m++) { X2a[m] = z2; X2b[m] = z2; }
#pragma unroll
    for (int j = 0; j < 4; j++)
#pragma unroll
        for (int m = 0; m < 4; m++) Xo[j][m] = 0.f;
    sb2[0] = z2; sb2[1] = z2;

    int mb = 0;   // mask buffer

    while (true) {
        const int b = row >> 5, h = row & 31;

#pragma unroll
        for (int k = 0; k < 8; k++) {
            cp_wait<2>();
            __syncthreads();   // tile k visible; buf (k+3)&3 free
            if (k < 5)            issue_tile(cur, k + 3);
            else if (hasnext)     issue_tile(nxt, k - 5);
            else                  cp_commit();   // keep group count uniform

            const int pair = k >> 2, ct = k & 3, buf = k & 3;

#pragma unroll
            for (int cc = 0; cc < CT; cc++) {
                const int c = ct * CT + cc;
                float4 W0 = *reinterpret_cast<const float4*>(&ring[buf][cc][e0]);
                float4 W1 = *reinterpret_cast<const float4*>(&ring[buf][cc][w0]);
                float4 W2 = *reinterpret_cast<const float4*>(&ring[buf][cc][e2]);

                ull wp[6] = {pk2(W0.x, W0.y), pk2(W0.z, W0.w),
                             pk2(W1.x, W1.y), pk2(W1.z, W1.w),
                             pk2(W2.x, W2.y), pk2(W2.z, W2.w)};
                ffma2(sb2[0], wp[2], wp[2]);
                ffma2(sb2[1], wp[3], wp[3]);

                const float win[12] = {W0.x, W0.y, W0.z, W0.w,
                                       W1.x, W1.y, W1.z, W1.w,
                                       W2.x, W2.y, W2.z, W2.w};
                const ull a01 = pk2(av[c].x, av[c].y);
                const ull a23 = pk2(av[c].z, av[c].w);

#pragma unroll
                for (int m = 0; m < 5; m++) {
                    ffma2(X2a[m], a01, wp[4 - m]);
                    ffma2(X2b[m], a23, wp[5 - m]);
                }
#pragma unroll
                for (int m = 0; m < 4; m++) {
                    Xo[0][m] = fmaf(av[c].x, win[7 - 2 * m],  Xo[0][m]);
                    Xo[1][m] = fmaf(av[c].y, win[8 - 2 * m],  Xo[1][m]);
                    Xo[2][m] = fmaf(av[c].z, win[9 - 2 * m],  Xo[2][m]);
                    Xo[3][m] = fmaf(av[c].w, win[10 - 2 * m], Xo[3][m]);
                }
            }

            if (ct == 3) {   // ---- pair epilogue --------------------------
                if (pair == 1 && hasnext) {
                    // Prefetch next row's A (av regs dead after tile 7) and
                    // masks into the other buffer; latency hides under epilogue.
#pragma unroll
                    for (int c = 0; c < CC; c++)
                        av[c] = *reinterpret_cast<const float4*>(
                            A + nxt + (size_t)c * HH * WW + w0);
                    unsigned mrow = (unsigned)(((nrow >> 5) * HH + (nrow & 31)) * WW);
                    float m4[4];
                    load_mask4f(MA, mrow + w0, mode, m4);
                    *reinterpret_cast<float4*>(&smA[mb ^ 1][w0]) =
                        make_float4(m4[0], m4[1], m4[2], m4[3]);
                    load_mask4f(MP, mrow + w0, mode, m4);
                    *reinterpret_cast<float4*>(&smF[mb ^ 1][0][w0]) =
                        make_float4(m4[0], m4[1], m4[2], m4[3]);
                    load_mask4f(MN, mrow + w0, mode, m4);
                    *reinterpret_cast<float4*>(&smF[mb ^ 1][1][w0]) =
                        make_float4(m4[0], m4[1], m4[2], m4[3]);
                }

                { float2 f0 = upk(sb2[0]), f1 = upk(sb2[1]);
                  *reinterpret_cast<float4*>(&sSb[w0]) =
                      make_float4(f0.x, f0.y, f1.x, f1.y); }
                __syncthreads();

                float X[4][NS];
#pragma unroll
                for (int m = 0; m < 5; m++) {
                    float2 fa = upk(X2a[m]), fb = upk(X2b[m]);
                    X[0][2 * m] = fa.x; X[1][2 * m] = fa.y;
                    X[2][2 * m] = fb.x; X[3][2 * m] = fb.y;
                }
#pragma unroll
                for (int m = 0; m < 4; m++) {
                    X[0][2 * m + 1] = Xo[0][m]; X[1][2 * m + 1] = Xo[1][m];
                    X[2][2 * m + 1] = Xo[2][m]; X[3][2 * m + 1] = Xo[3][m];
                }

                float4 S0 = *reinterpret_cast<const float4*>(&sSb[e0]);
                float4 S1 = *reinterpret_cast<const float4*>(&sSb[w0]);
                float4 S2 = *reinterpret_cast<const float4*>(&sSb[e2]);
                float swin[12] = {S0.x, S0.y, S0.z, S0.w,
                                  S1.x, S1.y, S1.z, S1.w,
                                  S2.x, S2.y, S2.z, S2.w};
                float4 M0 = *reinterpret_cast<const float4*>(&smF[mb][pair][e0]);
                float4 M1 = *reinterpret_cast<const float4*>(&smF[mb][pair][w0]);
                float4 M2 = *reinterpret_cast<const float4*>(&smF[mb][pair][e2]);
                float mwin[12] = {M0.x, M0.y, M0.z, M0.w,
                                  M1.x, M1.y, M1.z, M1.w,
                                  M2.x, M2.y, M2.z, M2.w};
                float4 ma4 = *reinterpret_cast<const float4*>(&smA[mb][w0]);
                float mam[4] = {ma4.x, ma4.y, ma4.z, ma4.w};

                float num[NS], cnt[NS];
#pragma unroll
                for (int s = 0; s < NS; s++) { num[s] = 0.f; cnt[s] = 0.f; }
#pragma unroll
                for (int j = 0; j < 4; j++)
#pragma unroll
                    for (int s = 0; s < NS; s++) {
                        const int idx = j + 8 - s;
                        float v  = fmaf(-2.f, X[j][s], Sa[j]) + swin[idx];
                        float mm = mam[j] * mwin[idx];
                        num[s] = fmaf(mm, v, num[s]);
                        cnt[s] += mm;
                    }

                // 3-level shuffle: lanes 0..3 hold stride-4 partials of 8.
#pragma unroll
                for (int s = 0; s < NS; s++) {
                    float vn = num[s], vc = cnt[s];
                    vn += __shfl_down_sync(0xffffffffu, vn, 16);
                    vc += __shfl_down_sync(0xffffffffu, vc, 16);
                    vn += __shfl_down_sync(0xffffffffu, vn, 8);
                    vc += __shfl_down_sync(0xffffffffu, vc, 8);
                    vn += __shfl_down_sync(0xffffffffu, vn, 4);
                    vc += __shfl_down_sync(0xffffffffu, vc, 4);
                    if (lane < 4) {
                        redN[pair][s][wid * 4 + lane] = vn;
                        redC[pair][s][wid * 4 + lane] = vc;
                    }
                }

                // reset accumulators for next pair / next row
#pragma unroll
                for (int m = 0; m < 5; m++) { X2a[m] = z2; X2b[m] = z2; }
#pragma unroll
                for (int j = 0; j < 4; j++)
#pragma unroll
                    for (int m = 0; m < 4; m++) Xo[j][m] = 0.f;
                sb2[0] = z2; sb2[1] = z2;
            }
        }

        // ---- row finish: fold 16 partials, write global slots -------------
        __syncthreads();
        if (t < 36) {
            const int pair = t / 18, rem = t - pair * 18;
            const int s = rem >> 1, typ = rem & 1;
            const float* src = typ ? &redC[pair][s][0] : &redN[pair][s][0];
            float4 v0 = *reinterpret_cast<const float4*>(src);
            float4 v1 = *reinterpret_cast<const float4*>(src + 4);
            float4 v2 = *reinterpret_cast<const float4*>(src + 8);
            float4 v3 = *reinterpret_cast<const float4*>(src + 12);
            float vs = ((v0.x + v0.y) + (v0.z + v0.w)) +
                       ((v1.x + v1.y) + (v1.z + v1.w)) +
                       ((v2.x + v2.y) + (v2.z + v2.w)) +
                       ((v3.x + v3.y) + (v3.z + v3.w));
            if (typ) g_pcnt[pair][b][s][h] = vs;
            else     g_pnum[pair][b][s][h] = vs;
        }

        if (!hasnext) break;

        // ---- advance to next row ------------------------------------------
        row = nrow; cur = nxt;
        nrow = row + GRIDX;
        hasnext = nrow < NROWS;
        nxt = hasnext ? row_base(nrow) : 0;
        mb ^= 1;

        // Sa from the prefetched av (arrived during the epilogue)
        {
            ull s0 = z2, s1 = z2;
#pragma unroll
            for (int c = 0; c < CC; c++) {
                ull va = pk2(av[c].x, av[c].y), vb = pk2(av[c].z, av[c].w);
                ffma2(s0, va, va); ffma2(s1, vb, vb);
            }
            float2 f = upk(s0); Sa[0] = f.x; Sa[1] = f.y;
            f = upk(s1);        Sa[2] = f.x; Sa[3] = f.y;
        }
    }
}

// ---------------------------------------------------------------------------
// Per-batch reduce: grid=BB, 9 warps; warp s reduces over h for both pairs.
// ---------------------------------------------------------------------------
__global__ void __launch_bounds__(288) perb_kernel() {
    __shared__ float d[2][NS];
    const int b = blockIdx.x;
    const int wid = threadIdx.x >> 5, lane = threadIdx.x & 31;

    if (wid < NS) {
        float n0 = g_pnum[0][b][wid][lane];
        float c0 = g_pcnt[0][b][wid][lane];
        float n1 = g_pnum[1][b][wid][lane];
        float c1 = g_pcnt[1][b][wid][lane];
#pragma unroll
        for (int o = 16; o > 0; o >>= 1) {
            n0 += __shfl_down_sync(0xffffffffu, n0, o);
            c0 += __shfl_down_sync(0xffffffffu, c0, o);
            n1 += __shfl_down_sync(0xffffffffu, n1, o);
            c1 += __shfl_down_sync(0xffffffffu, c1, o);
        }
        if (lane == 0) {
            d[0][wid] = n0 / (16.f * c0 + 0.001f);
            d[1][wid] = n1 / (16.f * c1 + 0.001f);
        }
    }
    __syncthreads();
    if (threadIdx.x == 0) {
        float lap = d[0][0], lan = d[1][0];
#pragma unroll
        for (int s = 1; s < NS; s++) {
            lap = fminf(lap, d[0][s]);
            lan = fminf(lan, d[1][s]);
        }
        g_bloss[b] = fmaxf(lap - lan + 0.15f, 0.f);
    }
}

// ---------------------------------------------------------------------------
__global__ void mean_kernel(float* __restrict__ out) {
    const int t = threadIdx.x;   // 64
    float v = g_bloss[t];
#pragma unroll
    for (int o = 16; o > 0; o >>= 1) v += __shfl_down_sync(0xffffffffu, v, o);
    __shared__ float warp0, warp1;
    if (t == 0)  warp0 = v;
    if (t == 32) warp1 = v;
    __syncthreads();
    if (t == 0) out[0] = (warp0 + warp1) / (float)BB;
}

// ---------------------------------------------------------------------------
extern "C" void kernel_launch(void* const* d_in, const int* in_sizes, int n_in,
                              void* d_out, int out_size) {
    const float* A  = (const float*)d_in[0];
    const float* P  = (const float*)d_in[1];
    const float* Nt = (const float*)d_in[2];
    const char*  MA = (const char*)d_in[3];
    const char*  MP = (const char*)d_in[4];
    const char*  MN = (const char*)d_in[5];
    float* out = (float*)d_out;

    loss_kernel<<<GRIDX, 128>>>(A, P, Nt, MA, MP, MN);
    perb_kernel<<<BB, 288>>>();
    mean_kernel<<<1, 64>>>(out);
}

// round 12
// speedup vs baseline: 1.3410x; 1.3410x over previous
#include <cuda_runtime.h>

#define BB 64
#define CC 16
#define HH 32
#define WW 512
#define NS 9    // shifts: off = s - 4
#define CG 8    // channels per cp.async group
#define NBUF 3  // ring buffers (16 KB each)

// Per-(pair,b,s,h) partials — pure writes, no zeroing / atomics.
__device__ float g_pnum[2][BB][NS][HH];
__device__ float g_pcnt[2][BB][NS][HH];
__device__ float g_bloss[BB];

typedef unsigned long long ull;

__device__ __forceinline__ void cp_async16(unsigned int sdst, const void* gsrc) {
    asm volatile("cp.async.cg.shared.global [%0], [%1], 16;\n" :: "r"(sdst), "l"(gsrc));
}
__device__ __forceinline__ void cp_commit() {
    asm volatile("cp.async.commit_group;\n" ::: "memory");
}
template <int N> __device__ __forceinline__ void cp_wait() {
    asm volatile("cp.async.wait_group %0;\n" :: "n"(N) : "memory");
}

// Packed fp32x2 helpers (sm_103a FFMA2 — PTX only)
__device__ __forceinline__ ull pk2(float lo, float hi) {
    ull r; asm("mov.b64 %0, {%1, %2};" : "=l"(r) : "f"(lo), "f"(hi)); return r;
}
__device__ __forceinline__ float2 upk(ull v) {
    float2 f; asm("mov.b64 {%0, %1}, %2;" : "=f"(f.x), "=f"(f.y) : "l"(v)); return f;
}
__device__ __forceinline__ void ffma2(ull& d, ull a, ull b) {
    asm("fma.rn.f32x2 %0, %1, %2, %0;" : "+l"(d) : "l"(a), "l"(b));
}

__device__ __forceinline__ void load_mask4f(const char* __restrict__ m, size_t base,
                                            int mode, float out[4]) {
    if (mode == 0) {
        uchar4 v = *reinterpret_cast<const uchar4*>(m + base);
        out[0] = v.x ? 1.f : 0.f; out[1] = v.y ? 1.f : 0.f;
        out[2] = v.z ? 1.f : 0.f; out[3] = v.w ? 1.f : 0.f;
    } else if (mode == 1) {
        int4 v = *reinterpret_cast<const int4*>(reinterpret_cast<const int*>(m) + base);
        out[0] = v.x ? 1.f : 0.f; out[1] = v.y ? 1.f : 0.f;
        out[2] = v.z ? 1.f : 0.f; out[3] = v.w ? 1.f : 0.f;
    } else {
        float4 v = *reinterpret_cast<const float4*>(reinterpret_cast<const float*>(m) + base);
        out[0] = v.x != 0.f ? 1.f : 0.f; out[1] = v.y != 0.f ? 1.f : 0.f;
        out[2] = v.z != 0.f ? 1.f : 0.f; out[3] = v.w != 0.f ? 1.f : 0.f;
    }
}

// ---------------------------------------------------------------------------
// One CTA per (b,h). 128 threads, 4 consecutive w per thread.
// f rows streamed as 16 KB 8-channel groups through a 3-buffer cp.async ring:
// only 4 wait/sync phases per row; 48 KB of DRAM traffic in flight per CTA.
// ---------------------------------------------------------------------------
__global__ void __launch_bounds__(128, 4) loss_kernel(
    const float* __restrict__ A, const float* __restrict__ P,
    const float* __restrict__ Nt,
    const char* __restrict__ MA, const char* __restrict__ MP,
    const char* __restrict__ MN)
{
    __shared__ __align__(16) float ring[NBUF][CG][WW];     // 48 KB
    __shared__ __align__(16) float sSb[WW];                // 2 KB
    __shared__ __align__(4)  unsigned char smA8[WW];       // 512 B
    __shared__ __align__(4)  unsigned char smF8[2][WW];    // 1 KB
    __shared__ float red_n[2][NS][4], red_c[2][NS][4];
    __shared__ unsigned int sflag[4];

    const int t  = threadIdx.x;
    const int b  = blockIdx.x >> 5;
    const int h  = blockIdx.x & 31;
    const int w0 = t * 4;
    const int e0 = (w0 - 4) & (WW - 1);
    const int e2 = (w0 + 4) & (WW - 1);

    const size_t row_off = ((size_t)b * CC * HH + h) * WW;
    const size_t mrow    = ((size_t)b * HH + h) * WW;

    // -- mask dtype sniff (identical deterministic result in every CTA) -----
    if (t < 64) {
        unsigned int w = reinterpret_cast<const unsigned int*>(MA)[t];
        unsigned int bf = __ballot_sync(0xffffffffu, w == 0x3F800000u);
        unsigned int bg = __ballot_sync(0xffffffffu, (w >> 8) != 0u);
        if ((t & 31) == 0) { sflag[t >> 5] = bf; sflag[2 + (t >> 5)] = bg; }
    }

    auto issue_group = [&](const float* F, int cbase, int buf) {
#pragma unroll
        for (int cc = 0; cc < CG; cc++)
            cp_async16((unsigned int)__cvta_generic_to_shared(&ring[buf][cc][w0]),
                       F + row_off + (size_t)(cbase + cc) * HH * WW + w0);
        cp_commit();
    };
    // Prologue: P[0:8]->buf0, P[8:16]->buf1, N[0:8]->buf2
    issue_group(P, 0, 0);
    issue_group(P, 8, 1);
    issue_group(Nt, 0, 2);
    __syncthreads();
    const int mode = (sflag[0] | sflag[1]) ? 2 : ((sflag[2] | sflag[3]) ? 0 : 1);

    // -- a row -> registers + packed Sa (LDGs overlap in-flight groups) -----
    float4 av[CC];
    float Sa[4];
    {
        ull s0 = pk2(0.f, 0.f), s1 = s0;
#pragma unroll
        for (int c = 0; c < CC; c++) {
            float4 v = *reinterpret_cast<const float4*>(A + row_off + (size_t)c * HH * WW + w0);
            av[c] = v;
            ull va = pk2(v.x, v.y), vb = pk2(v.z, v.w);
            ffma2(s0, va, va); ffma2(s1, vb, vb);
        }
        float2 f = upk(s0); Sa[0] = f.x; Sa[1] = f.y;
        f = upk(s1);        Sa[2] = f.x; Sa[3] = f.y;
    }

    // -- masks -> smem as u8 0/1 ---------------------------------------------
    {
        float m4[4];
        load_mask4f(MA, mrow + w0, mode, m4);
        *reinterpret_cast<uchar4*>(&smA8[w0]) =
            make_uchar4((unsigned char)m4[0], (unsigned char)m4[1],
                        (unsigned char)m4[2], (unsigned char)m4[3]);
        load_mask4f(MP, mrow + w0, mode, m4);
        *reinterpret_cast<uchar4*>(&smF8[0][w0]) =
            make_uchar4((unsigned char)m4[0], (unsigned char)m4[1],
                        (unsigned char)m4[2], (unsigned char)m4[3]);
        load_mask4f(MN, mrow + w0, mode, m4);
        *reinterpret_cast<uchar4*>(&smF8[1][w0]) =
            make_uchar4((unsigned char)m4[0], (unsigned char)m4[1],
                        (unsigned char)m4[2], (unsigned char)m4[3]);
    }

    // Accumulators: even s packed along j-pairs, odd s scalar.
    ull  X2a[5], X2b[5];
    float Xo[4][4];
    ull  sb2[2];
    const ull z2 = pk2(0.f, 0.f);
#pragma unroll
    for (int m = 0; m < 5; m++) { X2a[m] = z2; X2b[m] = z2; }
#pragma unroll
    for (int j = 0; j < 4; j++)
#pragma unroll
        for (int m = 0; m < 4; m++) Xo[j][m] = 0.f;
    sb2[0] = z2; sb2[1] = z2;

    // ---- compute one 8-channel group from ring[buf] -------------------------
    auto compute_group = [&](int buf, int cbase) {
#pragma unroll
        for (int cc = 0; cc < CG; cc++) {
            const int c = cbase + cc;
            float4 W0 = *reinterpret_cast<const float4*>(&ring[buf][cc][e0]);
            float4 W1 = *reinterpret_cast<const float4*>(&ring[buf][cc][w0]);
            float4 W2 = *reinterpret_cast<const float4*>(&ring[buf][cc][e2]);

            ull wp[6] = {pk2(W0.x, W0.y), pk2(W0.z, W0.w),
                         pk2(W1.x, W1.y), pk2(W1.z, W1.w),
                         pk2(W2.x, W2.y), pk2(W2.z, W2.w)};
            ffma2(sb2[0], wp[2], wp[2]);
            ffma2(sb2[1], wp[3], wp[3]);

            const float win[12] = {W0.x, W0.y, W0.z, W0.w,
                                   W1.x, W1.y, W1.z, W1.w,
                                   W2.x, W2.y, W2.z, W2.w};
            const ull a01 = pk2(av[c].x, av[c].y);
            const ull a23 = pk2(av[c].z, av[c].w);

#pragma unroll
            for (int m = 0; m < 5; m++) {
                ffma2(X2a[m], a01, wp[4 - m]);
                ffma2(X2b[m], a23, wp[5 - m]);
            }
#pragma unroll
            for (int m = 0; m < 4; m++) {
                Xo[0][m] = fmaf(av[c].x, win[7 - 2 * m],  Xo[0][m]);
                Xo[1][m] = fmaf(av[c].y, win[8 - 2 * m],  Xo[1][m]);
                Xo[2][m] = fmaf(av[c].z, win[9 - 2 * m],  Xo[2][m]);
                Xo[3][m] = fmaf(av[c].w, win[10 - 2 * m], Xo[3][m]);
            }
        }
    };

    // ---- pair epilogue -------------------------------------------------------
    auto epilogue = [&](int pair) {
        { float2 f0 = upk(sb2[0]), f1 = upk(sb2[1]);
          *reinterpret_cast<float4*>(&sSb[w0]) = make_float4(f0.x, f0.y, f1.x, f1.y); }
        __syncthreads();

        float X[4][NS];
#pragma unroll
        for (int m = 0; m < 5; m++) {
            float2 fa = upk(X2a[m]), fb = upk(X2b[m]);
            X[0][2 * m] = fa.x; X[1][2 * m] = fa.y;
            X[2][2 * m] = fb.x; X[3][2 * m] = fb.y;
        }
#pragma unroll
        for (int m = 0; m < 4; m++) {
            X[0][2 * m + 1] = Xo[0][m]; X[1][2 * m + 1] = Xo[1][m];
            X[2][2 * m + 1] = Xo[2][m]; X[3][2 * m + 1] = Xo[3][m];
        }

        float4 S0 = *reinterpret_cast<const float4*>(&sSb[e0]);
        float4 S1 = *reinterpret_cast<const float4*>(&sSb[w0]);
        float4 S2 = *reinterpret_cast<const float4*>(&sSb[e2]);
        float swin[12] = {S0.x, S0.y, S0.z, S0.w,
                          S1.x, S1.y, S1.z, S1.w,
                          S2.x, S2.y, S2.z, S2.w};
        uchar4 M0 = *reinterpret_cast<const uchar4*>(&smF8[pair][e0]);
        uchar4 M1 = *reinterpret_cast<const uchar4*>(&smF8[pair][w0]);
        uchar4 M2 = *reinterpret_cast<const uchar4*>(&smF8[pair][e2]);
        float mwin[12] = {(float)M0.x, (float)M0.y, (float)M0.z, (float)M0.w,
                          (float)M1.x, (float)M1.y, (float)M1.z, (float)M1.w,
                          (float)M2.x, (float)M2.y, (float)M2.z, (float)M2.w};
        uchar4 ma4 = *reinterpret_cast<const uchar4*>(&smA8[w0]);
        float mam[4] = {(float)ma4.x, (float)ma4.y, (float)ma4.z, (float)ma4.w};

        float num[NS], cnt[NS];
#pragma unroll
        for (int s = 0; s < NS; s++) { num[s] = 0.f; cnt[s] = 0.f; }
#pragma unroll
        for (int j = 0; j < 4; j++)
#pragma unroll
            for (int s = 0; s < NS; s++) {
                const int idx = j + 8 - s;
                float v  = fmaf(-2.f, X[j][s], Sa[j]) + swin[idx];
                float mm = mam[j] * mwin[idx];
                num[s] = fmaf(mm, v, num[s]);
                cnt[s] += mm;
            }

#pragma unroll
        for (int s = 0; s < NS; s++) {
            float vn = num[s], vc = cnt[s];
            for (int o = 16; o > 0; o >>= 1) {
                vn += __shfl_down_sync(0xffffffffu, vn, o);
                vc += __shfl_down_sync(0xffffffffu, vc, o);
            }
            if ((t & 31) == 0) {
                red_n[pair][s][t >> 5] = vn;
                red_c[pair][s][t >> 5] = vc;
            }
        }

        // reset accumulators for next pair
#pragma unroll
        for (int m = 0; m < 5; m++) { X2a[m] = z2; X2b[m] = z2; }
#pragma unroll
        for (int j = 0; j < 4; j++)
#pragma unroll
            for (int m = 0; m < 4; m++) Xo[j][m] = 0.f;
        sb2[0] = z2; sb2[1] = z2;
    };

    // ---- 4 phases per row ----------------------------------------------------
    // Phase 0: P[0:8]
    cp_wait<2>(); __syncthreads();
    compute_group(0, 0);

    // Phase 1: P[8:16]; issue N[8:16] into buf0 after the sync proves buf0 free
    cp_wait<1>(); __syncthreads();
    issue_group(Nt, 8, 0);
    compute_group(1, 8);
    epilogue(0);

    // Phase 2: N[0:8]
    cp_wait<1>(); __syncthreads();
    compute_group(2, 0);

    // Phase 3: N[8:16]
    cp_wait<0>(); __syncthreads();
    compute_group(0, 8);
    epilogue(1);

    __syncthreads();
    if (t < 36) {   // per-(b,h) partial slots (no atomics)
        const int pair = (t % 18) / 9, s = t % 9;
        if (t < 18) {
            g_pnum[pair][b][s][h] = red_n[pair][s][0] + red_n[pair][s][1] +
                                    red_n[pair][s][2] + red_n[pair][s][3];
        } else {
            g_pcnt[pair][b][s][h] = red_c[pair][s][0] + red_c[pair][s][1] +
                                    red_c[pair][s][2] + red_c[pair][s][3];
        }
    }
}

// ---------------------------------------------------------------------------
// Per-batch reduce: grid=BB, 9 warps; warp s reduces over h for both pairs.
// ---------------------------------------------------------------------------
__global__ void __launch_bounds__(288) perb_kernel() {
    __shared__ float d[2][NS];
    const int b = blockIdx.x;
    const int wid = threadIdx.x >> 5, lane = threadIdx.x & 31;

    if (wid < NS) {
        float n0 = g_pnum[0][b][wid][lane];
        float c0 = g_pcnt[0][b][wid][lane];
        float n1 = g_pnum[1][b][wid][lane];
        float c1 = g_pcnt[1][b][wid][lane];
#pragma unroll
        for (int o = 16; o > 0; o >>= 1) {
            n0 += __shfl_down_sync(0xffffffffu, n0, o);
            c0 += __shfl_down_sync(0xffffffffu, c0, o);
            n1 += __shfl_down_sync(0xffffffffu, n1, o);
            c1 += __shfl_down_sync(0xffffffffu, c1, o);
        }
        if (lane == 0) {
            d[0][wid] = n0 / (16.f * c0 + 0.001f);
            d[1][wid] = n1 / (16.f * c1 + 0.001f);
        }
    }
    __syncthreads();
    if (threadIdx.x == 0) {
        float lap = d[0][0], lan = d[1][0];
#pragma unroll
        for (int s = 1; s < NS; s++) {
            lap = fminf(lap, d[0][s]);
            lan = fminf(lan, d[1][s]);
        }
        g_bloss[b] = fmaxf(lap - lan + 0.15f, 0.f);
    }
}

// ---------------------------------------------------------------------------
__global__ void mean_kernel(float* __restrict__ out) {
    const int t = threadIdx.x;   // 64
    float v = g_bloss[t];
#pragma unroll
    for (int o = 16; o > 0; o >>= 1) v += __shfl_down_sync(0xffffffffu, v, o);
    __shared__ float warp0, warp1;
    if (t == 0)  warp0 = v;
    if (t == 32) warp1 = v;
    __syncthreads();
    if (t == 0) out[0] = (warp0 + warp1) / (float)BB;
}

// ---------------------------------------------------------------------------
extern "C" void kernel_launch(void* const* d_in, const int* in_sizes, int n_in,
                              void* d_out, int out_size) {
    const float* A  = (const float*)d_in[0];
    const float* P  = (const float*)d_in[1];
    const float* Nt = (const float*)d_in[2];
    const char*  MA = (const char*)d_in[3];
    const char*  MP = (const char*)d_in[4];
    const char*  MN = (const char*)d_in[5];
    float* out = (float*)d_out;

    loss_kernel<<<BB * HH, 128>>>(A, P, Nt, MA, MP, MN);
    perb_kernel<<<BB, 288>>>();
    mean_kernel<<<1, 64>>>(out);
}

// round 13
// speedup vs baseline: 1.4356x; 1.0705x over previous
#include <cuda_runtime.h>

#define BB 64
#define CC 16
#define HH 32
#define WW 512
#define NS 9    // shifts: off = s - 4
#define CT 4    // channels per cp.async tile
#define NBUF 5  // ring buffers (8 KB each): 4 tiles in flight during compute

// Per-(pair,b,s,h) partials — pure writes, no zeroing / atomics.
__device__ float g_pnum[2][BB][NS][HH];
__device__ float g_pcnt[2][BB][NS][HH];
__device__ float g_bloss[BB];

typedef unsigned long long ull;

__device__ __forceinline__ void cp_async16(unsigned int sdst, const void* gsrc) {
    asm volatile("cp.async.cg.shared.global [%0], [%1], 16;\n" :: "r"(sdst), "l"(gsrc));
}
__device__ __forceinline__ void cp_commit() {
    asm volatile("cp.async.commit_group;\n" ::: "memory");
}
template <int N> __device__ __forceinline__ void cp_wait() {
    asm volatile("cp.async.wait_group %0;\n" :: "n"(N) : "memory");
}

// Packed fp32x2 helpers (sm_103a FFMA2 — PTX only)
__device__ __forceinline__ ull pk2(float lo, float hi) {
    ull r; asm("mov.b64 %0, {%1, %2};" : "=l"(r) : "f"(lo), "f"(hi)); return r;
}
__device__ __forceinline__ float2 upk(ull v) {
    float2 f; asm("mov.b64 {%0, %1}, %2;" : "=f"(f.x), "=f"(f.y) : "l"(v)); return f;
}
__device__ __forceinline__ void ffma2(ull& d, ull a, ull b) {
    asm("fma.rn.f32x2 %0, %1, %2, %0;" : "+l"(d) : "l"(a), "l"(b));
}

__device__ __forceinline__ void load_mask4f(const char* __restrict__ m, size_t base,
                                            int mode, float out[4]) {
    if (mode == 0) {
        uchar4 v = *reinterpret_cast<const uchar4*>(m + base);
        out[0] = v.x ? 1.f : 0.f; out[1] = v.y ? 1.f : 0.f;
        out[2] = v.z ? 1.f : 0.f; out[3] = v.w ? 1.f : 0.f;
    } else if (mode == 1) {
        int4 v = *reinterpret_cast<const int4*>(reinterpret_cast<const int*>(m) + base);
        out[0] = v.x ? 1.f : 0.f; out[1] = v.y ? 1.f : 0.f;
        out[2] = v.z ? 1.f : 0.f; out[3] = v.w ? 1.f : 0.f;
    } else {
        float4 v = *reinterpret_cast<const float4*>(reinterpret_cast<const float*>(m) + base);
        out[0] = v.x != 0.f ? 1.f : 0.f; out[1] = v.y != 0.f ? 1.f : 0.f;
        out[2] = v.z != 0.f ? 1.f : 0.f; out[3] = v.w != 0.f ? 1.f : 0.f;
    }
}

// ---------------------------------------------------------------------------
// One CTA per (b,h). 128 threads, 4 consecutive w per thread.
// f rows streamed as 8 KB channel-tiles through a depth-4, 5-buffer cp.async
// ring (R4 structure; deeper pipeline).
// ---------------------------------------------------------------------------
__global__ void __launch_bounds__(128, 4) loss_kernel(
    const float* __restrict__ A, const float* __restrict__ P,
    const float* __restrict__ Nt,
    const char* __restrict__ MA, const char* __restrict__ MP,
    const char* __restrict__ MN)
{
    __shared__ __align__(16) float ring[NBUF][CT][WW];   // 40 KB
    __shared__ __align__(16) float sSb[WW];              // 2 KB
    __shared__ __align__(16) float smA[WW];              // 2 KB
    __shared__ __align__(16) float smF[2][WW];           // 4 KB
    __shared__ float red_n[2][NS][4], red_c[2][NS][4];
    __shared__ unsigned int sflag[4];

    const int t  = threadIdx.x;
    const int b  = blockIdx.x >> 5;
    const int h  = blockIdx.x & 31;
    const int w0 = t * 4;
    const int e0 = (w0 - 4) & (WW - 1);
    const int e2 = (w0 + 4) & (WW - 1);

    const size_t row_off = ((size_t)b * CC * HH + h) * WW;
    const size_t mrow    = ((size_t)b * HH + h) * WW;

    // -- mask dtype sniff (identical deterministic result in every CTA) -----
    if (t < 64) {
        unsigned int w = reinterpret_cast<const unsigned int*>(MA)[t];
        unsigned int bf = __ballot_sync(0xffffffffu, w == 0x3F800000u);
        unsigned int bg = __ballot_sync(0xffffffffu, (w >> 8) != 0u);
        if ((t & 31) == 0) { sflag[t >> 5] = bf; sflag[2 + (t >> 5)] = bg; }
    }

    auto issue_tile = [&](int k) {   // tile k (0..7): P tiles 0-3, N tiles 4-7
        const float* F = (k >= 4) ? Nt : P;
        const int ct = k & 3, buf = k % NBUF;
#pragma unroll
        for (int cc = 0; cc < CT; cc++)
            cp_async16((unsigned int)__cvta_generic_to_shared(&ring[buf][cc][w0]),
                       F + row_off + (size_t)(ct * CT + cc) * HH * WW + w0);
        cp_commit();
    };
    issue_tile(0); issue_tile(1); issue_tile(2); issue_tile(3);
    __syncthreads();
    const int mode = (sflag[0] | sflag[1]) ? 2 : ((sflag[2] | sflag[3]) ? 0 : 1);

    // -- a row -> registers + packed Sa (LDGs overlap in-flight tiles) ------
    float4 av[CC];
    ull Sa2[2] = {pk2(0.f, 0.f), pk2(0.f, 0.f)};
#pragma unroll
    for (int c = 0; c < CC; c++) {
        float4 v = *reinterpret_cast<const float4*>(A + row_off + (size_t)c * HH * WW + w0);
        av[c] = v;
        ull va = pk2(v.x, v.y), vb = pk2(v.z, v.w);
        ffma2(Sa2[0], va, va);
        ffma2(Sa2[1], vb, vb);
    }
    float Sa[4];
    { float2 f = upk(Sa2[0]); Sa[0] = f.x; Sa[1] = f.y;
      f = upk(Sa2[1]);        Sa[2] = f.x; Sa[3] = f.y; }

    // -- masks -> smem as 0/1 floats ----------------------------------------
    {
        float m4[4];
        load_mask4f(MA, mrow + w0, mode, m4);
        *reinterpret_cast<float4*>(&smA[w0]) = make_float4(m4[0], m4[1], m4[2], m4[3]);
        load_mask4f(MP, mrow + w0, mode, m4);
        *reinterpret_cast<float4*>(&smF[0][w0]) = make_float4(m4[0], m4[1], m4[2], m4[3]);
        load_mask4f(MN, mrow + w0, mode, m4);
        *reinterpret_cast<float4*>(&smF[1][w0]) = make_float4(m4[0], m4[1], m4[2], m4[3]);
    }

    // Accumulators: even s packed along j-pairs, odd s scalar.
    ull  X2a[5], X2b[5];
    float Xo[4][4];
    ull  sb2[2];
    const ull z2 = pk2(0.f, 0.f);
#pragma unroll
    for (int m = 0; m < 5; m++) { X2a[m] = z2; X2b[m] = z2; }
#pragma unroll
    for (int j = 0; j < 4; j++)
#pragma unroll
        for (int m = 0; m < 4; m++) Xo[j][m] = 0.f;
    sb2[0] = z2; sb2[1] = z2;

    // -- main tile loop: 8 tiles = (P 0..3, N 0..3), depth-4 pipeline -------
#pragma unroll
    for (int k = 0; k < 8; k++) {
        if (k <= 4)      cp_wait<3>();
        else if (k == 5) cp_wait<2>();
        else if (k == 6) cp_wait<1>();
        else             cp_wait<0>();
        __syncthreads();               // tile k visible; tile k-1's buf drained
        if (k < 4) issue_tile(k + 4);  // reuses buf (k-1)%5 — safe after sync

        const int pair = k >> 2, ct = k & 3, buf = k % NBUF;

#pragma unroll
        for (int cc = 0; cc < CT; cc++) {
            const int c = ct * CT + cc;
            float4 W0 = *reinterpret_cast<const float4*>(&ring[buf][cc][e0]);
            float4 W1 = *reinterpret_cast<const float4*>(&ring[buf][cc][w0]);
            float4 W2 = *reinterpret_cast<const float4*>(&ring[buf][cc][e2]);

            ull wp[6] = {pk2(W0.x, W0.y), pk2(W0.z, W0.w),
                         pk2(W1.x, W1.y), pk2(W1.z, W1.w),
                         pk2(W2.x, W2.y), pk2(W2.z, W2.w)};
            ffma2(sb2[0], wp[2], wp[2]);
            ffma2(sb2[1], wp[3], wp[3]);

            const float win[12] = {W0.x, W0.y, W0.z, W0.w,
                                   W1.x, W1.y, W1.z, W1.w,
                                   W2.x, W2.y, W2.z, W2.w};
            const ull a01 = pk2(av[c].x, av[c].y);
            const ull a23 = pk2(av[c].z, av[c].w);

#pragma unroll
            for (int m = 0; m < 5; m++) {
                ffma2(X2a[m], a01, wp[4 - m]);
                ffma2(X2b[m], a23, wp[5 - m]);
            }
#pragma unroll
            for (int m = 0; m < 4; m++) {
                Xo[0][m] = fmaf(av[c].x, win[7 - 2 * m],  Xo[0][m]);
                Xo[1][m] = fmaf(av[c].y, win[8 - 2 * m],  Xo[1][m]);
                Xo[2][m] = fmaf(av[c].z, win[9 - 2 * m],  Xo[2][m]);
                Xo[3][m] = fmaf(av[c].w, win[10 - 2 * m], Xo[3][m]);
            }
        }

        if (ct == 3) {   // pair epilogue (overlaps in-flight N tiles)
            { float2 f0 = upk(sb2[0]), f1 = upk(sb2[1]);
              *reinterpret_cast<float4*>(&sSb[w0]) = make_float4(f0.x, f0.y, f1.x, f1.y); }
            __syncthreads();

            float X[4][NS];
#pragma unroll
            for (int m = 0; m < 5; m++) {
                float2 fa = upk(X2a[m]), fb = upk(X2b[m]);
                X[0][2 * m] = fa.x; X[1][2 * m] = fa.y;
                X[2][2 * m] = fb.x; X[3][2 * m] = fb.y;
            }
#pragma unroll
            for (int m = 0; m < 4; m++) {
                X[0][2 * m + 1] = Xo[0][m]; X[1][2 * m + 1] = Xo[1][m];
                X[2][2 * m + 1] = Xo[2][m]; X[3][2 * m + 1] = Xo[3][m];
            }

            float4 S0 = *reinterpret_cast<const float4*>(&sSb[e0]);
            float4 S1 = *reinterpret_cast<const float4*>(&sSb[w0]);
            float4 S2 = *reinterpret_cast<const float4*>(&sSb[e2]);
            float swin[12] = {S0.x, S0.y, S0.z, S0.w,
                              S1.x, S1.y, S1.z, S1.w,
                              S2.x, S2.y, S2.z, S2.w};
            float4 M0 = *reinterpret_cast<const float4*>(&smF[pair][e0]);
            float4 M1 = *reinterpret_cast<const float4*>(&smF[pair][w0]);
            float4 M2 = *reinterpret_cast<const float4*>(&smF[pair][e2]);
            float mwin[12] = {M0.x, M0.y, M0.z, M0.w,
                              M1.x, M1.y, M1.z, M1.w,
                              M2.x, M2.y, M2.z, M2.w};
            float4 ma4 = *reinterpret_cast<const float4*>(&smA[w0]);
            float mam[4] = {ma4.x, ma4.y, ma4.z, ma4.w};

            float num[NS], cnt[NS];
#pragma unroll
            for (int s = 0; s < NS; s++) { num[s] = 0.f; cnt[s] = 0.f; }
#pragma unroll
            for (int j = 0; j < 4; j++)
#pragma unroll
                for (int s = 0; s < NS; s++) {
                    const int idx = j + 8 - s;
                    float v  = fmaf(-2.f, X[j][s], Sa[j]) + swin[idx];
                    float mm = mam[j] * mwin[idx];
                    num[s] = fmaf(mm, v, num[s]);
                    cnt[s] += mm;
                }

#pragma unroll
            for (int s = 0; s < NS; s++) {
                float vn = num[s], vc = cnt[s];
                for (int o = 16; o > 0; o >>= 1) {
                    vn += __shfl_down_sync(0xffffffffu, vn, o);
                    vc += __shfl_down_sync(0xffffffffu, vc, o);
                }
                if ((t & 31) == 0) {
                    red_n[pair][s][t >> 5] = vn;
                    red_c[pair][s][t >> 5] = vc;
                }
            }

            // reset accumulators for next pair
#pragma unroll
            for (int m = 0; m < 5; m++) { X2a[m] = z2; X2b[m] = z2; }
#pragma unroll
            for (int j = 0; j < 4; j++)
#pragma unroll
                for (int m = 0; m < 4; m++) Xo[j][m] = 0.f;
            sb2[0] = z2; sb2[1] = z2;
        }
    }

    __syncthreads();
    if (t < 36) {   // per-(b,h) partial slots (no atomics)
        const int pair = (t % 18) / 9, s = t % 9;
        if (t < 18) {
            g_pnum[pair][b][s][h] = red_n[pair][s][0] + red_n[pair][s][1] +
                                    red_n[pair][s][2] + red_n[pair][s][3];
        } else {
            g_pcnt[pair][b][s][h] = red_c[pair][s][0] + red_c[pair][s][1] +
                                    red_c[pair][s][2] + red_c[pair][s][3];
        }
    }
}

// ---------------------------------------------------------------------------
// Per-batch reduce: grid=BB, 9 warps; warp s reduces over h for both pairs.
// ---------------------------------------------------------------------------
__global__ void __launch_bounds__(288) perb_kernel() {
    __shared__ float d[2][NS];
    const int b = blockIdx.x;
    const int wid = threadIdx.x >> 5, lane = threadIdx.x & 31;

    if (wid < NS) {
        float n0 = g_pnum[0][b][wid][lane];
        float c0 = g_pcnt[0][b][wid][lane];
        float n1 = g_pnum[1][b][wid][lane];
        float c1 = g_pcnt[1][b][wid][lane];
#pragma unroll
        for (int o = 16; o > 0; o >>= 1) {
            n0 += __shfl_down_sync(0xffffffffu, n0, o);
            c0 += __shfl_down_sync(0xffffffffu, c0, o);
            n1 += __shfl_down_sync(0xffffffffu, n1, o);
            c1 += __shfl_down_sync(0xffffffffu, c1, o);
        }
        if (lane == 0) {
            d[0][wid] = n0 / (16.f * c0 + 0.001f);
            d[1][wid] = n1 / (16.f * c1 + 0.001f);
        }
    }
    __syncthreads();
    if (threadIdx.x == 0) {
        float lap = d[0][0], lan = d[1][0];
#pragma unroll
        for (int s = 1; s < NS; s++) {
            lap = fminf(lap, d[0][s]);
            lan = fminf(lan, d[1][s]);
        }
        g_bloss[b] = fmaxf(lap - lan + 0.15f, 0.f);
    }
}

// ---------------------------------------------------------------------------
__global__ void mean_kernel(float* __restrict__ out) {
    const int t = threadIdx.x;   // 64
    float v = g_bloss[t];
#pragma unroll
    for (int o = 16; o > 0; o >>= 1) v += __shfl_down_sync(0xffffffffu, v, o);
    __shared__ float warp0, warp1;
    if (t == 0)  warp0 = v;
    if (t == 32) warp1 = v;
    __syncthreads();
    if (t == 0) out[0] = (warp0 + warp1) / (float)BB;
}

// ---------------------------------------------------------------------------
extern "C" void kernel_launch(void* const* d_in, const int* in_sizes, int n_in,
                              void* d_out, int out_size) {
    const float* A  = (const float*)d_in[0];
    const float* P  = (const float*)d_in[1];
    const float* Nt = (const float*)d_in[2];
    const char*  MA = (const char*)d_in[3];
    const char*  MP = (const char*)d_in[4];
    const char*  MN = (const char*)d_in[5];
    float* out = (float*)d_out;

    loss_kernel<<<BB * HH, 128>>>(A, P, Nt, MA, MP, MN);
    perb_kernel<<<BB, 288>>>();
    mean_kernel<<<1, 64>>>(out);
}